// round 5
// baseline (speedup 1.0000x reference)
#include <cuda_runtime.h>
#include <cuda_fp16.h>
#include <cstdint>

#define NT 256
#define SA 136            // A smem row stride (halves)
#define B_ 512
#define NINT 1023

// smem byte offsets
#define OFF_AH 0
#define OFF_AL 17408
#define OFF_B0 34816      // chunk buf 0: [Wh 128x40][Wl 128x40]
#define OFF_B1 55296
#define SMEM_TOTAL 75776

// Weight chunk streams: chunk = 8192 halves = [hi: 128n x 32k][lo: 128n x 32k]
// leaf: L0 has K=64 -> 2 chunks, L1..L5 4 chunks each -> 22 chunks
// int : all layers K=128(padded) -> 24 chunks
__device__ __align__(16) __half g_leaf_W[22 * 8192];
__device__ __align__(16) __half g_int_W[24 * 8192];
__device__ float g_leaf_bias[768];
__device__ float g_int_bias[768];

// Ping-pong activation buffers (fp32, 33 ch per node)
__device__ float g_curA[(size_t)B_ * 1024 * 33];
__device__ float g_curB[(size_t)B_ * 512 * 33];

// ---------------------------------------------------------------------------
// Prep: bake weights into chunked hi/lo fp16 streams + padded biases.
// ---------------------------------------------------------------------------
__global__ void prep_kernel(
    const float* __restrict__ lWin,  const float* __restrict__ lbin,
    const float* __restrict__ lWhid, const float* __restrict__ lbhid,
    const float* __restrict__ lWout, const float* __restrict__ lbout,
    const float* __restrict__ iWin,  const float* __restrict__ ibin,
    const float* __restrict__ iWhid, const float* __restrict__ ibhid,
    const float* __restrict__ iWout, const float* __restrict__ ibout)
{
    const int NLEAF = 22 * 8192;
    const int NINTW = 24 * 8192;
    const int total = NLEAF + NINTW + 1536;
    for (int i = blockIdx.x * blockDim.x + threadIdx.x; i < total;
         i += gridDim.x * blockDim.x) {
        if (i < NLEAF) {
            int gch = i >> 13;
            int rem = i & 8191;
            int mat = rem >> 12;
            int n   = (rem >> 5) & 127;
            int k   = rem & 31;
            int l, kc;
            if (gch < 2) { l = 0; kc = gch; }
            else         { l = 1 + ((gch - 2) >> 2); kc = (gch - 2) & 3; }
            int Kg = kc * 32 + k;
            float v;
            if (l == 0)      v = lWin[Kg * 128 + n];
            else if (l < 5)  v = lWhid[(l - 1) * 16384 + Kg * 128 + n];
            else             v = (n < 33) ? lWout[Kg * 33 + n] : 0.f;
            __half h = __float2half_rn(v);
            g_leaf_W[i] = (mat == 0) ? h : __float2half_rn(v - __half2float(h));
        } else if (i < NLEAF + NINTW) {
            int i2 = i - NLEAF;
            int gch = i2 >> 13;
            int rem = i2 & 8191;
            int mat = rem >> 12;
            int n   = (rem >> 5) & 127;
            int k   = rem & 31;
            int l = gch >> 2, kc = gch & 3;
            int Kg = kc * 32 + k;
            float v;
            if (l == 0)      v = (Kg < 98) ? iWin[Kg * 128 + n] : 0.f;
            else if (l < 5)  v = iWhid[(l - 1) * 16384 + Kg * 128 + n];
            else             v = (n < 33) ? iWout[Kg * 33 + n] : 0.f;
            __half h = __float2half_rn(v);
            g_int_W[i2] = (mat == 0) ? h : __float2half_rn(v - __half2float(h));
        } else {
            int i3 = i - NLEAF - NINTW;     // 0..1535
            int j = (i3 < 768) ? i3 : i3 - 768;
            int l = j >> 7, c = j & 127;
            float v;
            if (i3 < 768) {
                if (l == 0)      v = lbin[c];
                else if (l < 5)  v = lbhid[(l - 1) * 128 + c];
                else             v = (c < 33) ? lbout[c] : 0.f;
                g_leaf_bias[j] = v;
            } else {
                if (l == 0)      v = ibin[c];
                else if (l < 5)  v = ibhid[(l - 1) * 128 + c];
                else             v = (c < 33) ? ibout[c] : 0.f;
                g_int_bias[j] = v;
            }
        }
    }
}

// ---------------------------------------------------------------------------
// PTX helpers
// ---------------------------------------------------------------------------
__device__ __forceinline__ void mma16816(float* c, const uint32_t* a,
                                         uint32_t b0, uint32_t b1)
{
    asm volatile(
        "mma.sync.aligned.m16n8k16.row.col.f32.f16.f16.f32 "
        "{%0,%1,%2,%3}, {%4,%5,%6,%7}, {%8,%9}, {%0,%1,%2,%3};\n"
        : "+f"(c[0]), "+f"(c[1]), "+f"(c[2]), "+f"(c[3])
        : "r"(a[0]), "r"(a[1]), "r"(a[2]), "r"(a[3]), "r"(b0), "r"(b1));
}

__device__ __forceinline__ void ldsm4(uint32_t* r, uint32_t addr)
{
    asm volatile("ldmatrix.sync.aligned.m8n8.x4.shared.b16 {%0,%1,%2,%3}, [%4];"
                 : "=r"(r[0]), "=r"(r[1]), "=r"(r[2]), "=r"(r[3]) : "r"(addr));
}

__device__ __forceinline__ void cpa16(uint32_t dst, const void* src)
{
    asm volatile("cp.async.cg.shared.global [%0], [%1], 16;" :: "r"(dst), "l"(src));
}
__device__ __forceinline__ void cpa_commit() { asm volatile("cp.async.commit_group;"); }

// stage one k32 chunk (16KB) into a smem buffer (row stride 40 halves)
__device__ __forceinline__ void stage_chunk(uint32_t sbuf, const __half* gW, int g)
{
    const char* src = (const char*)gW + (size_t)g * 16384;
    const int t = threadIdx.x;
    #pragma unroll
    for (int u = 0; u < 4; ++u) {
        int i = t + u * 256;            // 0..1023
        int mat = i >> 9;
        int n   = (i >> 2) & 127;
        int kq  = i & 3;
        cpa16(sbuf + (uint32_t)(mat * 10240 + n * 80 + kq * 16), src + i * 16);
    }
}

// ---------------------------------------------------------------------------
// 6-layer MLP for 64 rows in smem. 8 warps, warp tile m32n32, split-fp16
// 3-MMA fp32 emulation, K-chunked double-buffered weight stream.
// Caller must have issued stage_chunk(buf0, gW, 0); commit; stage(buf1,1); commit.
// ---------------------------------------------------------------------------
__device__ __forceinline__ void run_unit(
    char* smem, uint32_t sb, const __half* gW, const float* gbias,
    int nc0, float* gout, float* dfinal, int row0)
{
    const int tid  = threadIdx.x;
    const int warp = tid >> 5;
    const int lane = tid & 31;
    const int wm = warp >> 2;      // 0..1 (32-row block)
    const int wn = warp & 3;       // 0..3 (32-col block)
    const int gid = lane >> 2;
    const int tig = lane & 3;

    __half* sAh = (__half*)(smem + OFF_AH);
    __half* sAl = (__half*)(smem + OFF_AL);
    const uint32_t uAh = sb + OFF_AH, uAl = sb + OFF_AL;

    const int aRow = wm * 32 + (lane & 15);
    const uint32_t offA = (uint32_t)(aRow * SA + ((lane >> 4) << 3)) * 2u;
    const int wRowBase = wn * 32 + ((lane >> 4) << 3) + (lane & 7);
    const uint32_t offW = (uint32_t)(wRowBase * 40 + (((lane >> 3) & 1) << 3)) * 2u;

    const int total = nc0 + 20;
    int g = 0;
    #pragma unroll 1
    for (int l = 0; l < 6; ++l) {
        const int nc = l ? 4 : nc0;
        const int Np = (l < 5) ? 128 : 40;
        int ntc = (Np - wn * 32 + 7) >> 3;
        if (ntc < 0) ntc = 0;
        if (ntc > 4) ntc = 4;

        float C[2][4][4];
        #pragma unroll
        for (int mt = 0; mt < 2; ++mt)
            #pragma unroll
            for (int nt = 0; nt < 4; ++nt)
                #pragma unroll
                for (int q = 0; q < 4; ++q) C[mt][nt][q] = 0.f;

        #pragma unroll 1
        for (int c = 0; c < nc; ++c, ++g) {
            asm volatile("cp.async.wait_group 1;" ::: "memory");
            __syncthreads();
            const uint32_t wb = sb + ((g & 1) ? OFF_B1 : OFF_B0);

            if (ntc > 0) {
                #pragma unroll
                for (int ks = 0; ks < 2; ++ks) {
                    const uint32_t ka = (uint32_t)(c * 32 + ks * 16) * 2u;
                    uint32_t ah[2][4], al[2][4], wh[2][4], wl[2][4];
                    ldsm4(ah[0], uAh + offA + ka);
                    ldsm4(ah[1], uAh + offA + ka + 4352u);
                    ldsm4(al[0], uAl + offA + ka);
                    ldsm4(al[1], uAl + offA + ka + 4352u);
                    const uint32_t wadr = wb + offW + (uint32_t)ks * 32u;
                    ldsm4(wh[0], wadr);
                    ldsm4(wl[0], wadr + 10240u);
                    if (ntc > 2) {
                        ldsm4(wh[1], wadr + 1280u);
                        ldsm4(wl[1], wadr + 11520u);
                    }
                    #pragma unroll
                    for (int nt = 0; nt < 4; ++nt) {
                        if (nt < ntc) {
                            const int p = nt >> 1, q = (nt & 1) << 1;
                            uint32_t b0h = wh[p][q], b1h = wh[p][q + 1];
                            uint32_t b0l = wl[p][q], b1l = wl[p][q + 1];
                            #pragma unroll
                            for (int mt = 0; mt < 2; ++mt) {
                                mma16816(C[mt][nt], ah[mt], b0h, b1h);
                                mma16816(C[mt][nt], ah[mt], b0l, b1l);
                                mma16816(C[mt][nt], al[mt], b0h, b1h);
                            }
                        }
                    }
                }
            }
            __syncthreads();
            if (g + 2 < total) stage_chunk(wb, gW, g + 2);
            cpa_commit();
        }

        // ---- epilogue ----
        if (l < 5) {
            #pragma unroll
            for (int mt = 0; mt < 2; ++mt) {
                #pragma unroll
                for (int nt = 0; nt < 4; ++nt) {
                    if (nt < ntc) {
                        int r  = wm * 32 + mt * 16 + gid;
                        int cb = wn * 32 + nt * 8 + tig * 2;
                        float bb0 = gbias[l * 128 + cb];
                        float bb1 = gbias[l * 128 + cb + 1];
                        float v00 = fmaxf(C[mt][nt][0] + bb0, 0.f);
                        float v01 = fmaxf(C[mt][nt][1] + bb1, 0.f);
                        float v10 = fmaxf(C[mt][nt][2] + bb0, 0.f);
                        float v11 = fmaxf(C[mt][nt][3] + bb1, 0.f);
                        __half h00 = __float2half_rn(v00), h01 = __float2half_rn(v01);
                        __half h10 = __float2half_rn(v10), h11 = __float2half_rn(v11);
                        __half e00 = __float2half_rn(v00 - __half2float(h00));
                        __half e01 = __float2half_rn(v01 - __half2float(h01));
                        __half e10 = __float2half_rn(v10 - __half2float(h10));
                        __half e11 = __float2half_rn(v11 - __half2float(h11));
                        *(__half2*)(sAh + r * SA + cb)       = __halves2half2(h00, h01);
                        *(__half2*)(sAh + (r + 8) * SA + cb) = __halves2half2(h10, h11);
                        *(__half2*)(sAl + r * SA + cb)       = __halves2half2(e00, e01);
                        *(__half2*)(sAl + (r + 8) * SA + cb) = __halves2half2(e10, e11);
                    }
                }
            }
        } else {
            #pragma unroll
            for (int mt = 0; mt < 2; ++mt) {
                #pragma unroll
                for (int nt = 0; nt < 4; ++nt) {
                    if (nt < ntc) {
                        int r  = wm * 32 + mt * 16 + gid;
                        int cb = wn * 32 + nt * 8 + tig * 2;
                        float bb0 = gbias[640 + cb];
                        float bb1 = gbias[640 + cb + 1];
                        float v00 = C[mt][nt][0] + bb0;
                        float v01 = C[mt][nt][1] + bb1;
                        float v10 = C[mt][nt][2] + bb0;
                        float v11 = C[mt][nt][3] + bb1;
                        if (dfinal) {
                            if (cb == 0) {
                                dfinal[row0 + r]     = v00;
                                dfinal[row0 + r + 8] = v10;
                            }
                        } else {
                            size_t ro = (size_t)(row0 + r) * 33;
                            size_t r8 = (size_t)(row0 + r + 8) * 33;
                            if (cb < 33)     { gout[ro + cb]     = v00; gout[r8 + cb]     = v10; }
                            if (cb + 1 < 33) { gout[ro + cb + 1] = v01; gout[r8 + cb + 1] = v11; }
                        }
                    }
                }
            }
        }
    }
}

// ---------------------------------------------------------------------------
// Leaf kernel: 64 rows/CTA of leaf_feat (K=64) -> cur (33 ch, fp32)
// ---------------------------------------------------------------------------
__global__ void __launch_bounds__(NT, 3)
leaf_kernel(const float* __restrict__ leaf_feat, float* __restrict__ curOut)
{
    extern __shared__ char smem[];
    const uint32_t sb = (uint32_t)__cvta_generic_to_shared(smem);
    const int tid = threadIdx.x;
    const int row0 = blockIdx.x * 64;

    stage_chunk(sb + OFF_B0, g_leaf_W, 0); cpa_commit();
    stage_chunk(sb + OFF_B1, g_leaf_W, 1); cpa_commit();

    __half* sAh = (__half*)(smem + OFF_AH);
    __half* sAl = (__half*)(smem + OFF_AL);
    for (int i = tid; i < 64 * 16; i += NT) {
        int r = i >> 4, c4 = i & 15;
        float4 v = ((const float4*)(leaf_feat + (size_t)(row0 + r) * 64))[c4];
        int c = c4 * 4;
        __half h0 = __float2half_rn(v.x), h1 = __float2half_rn(v.y);
        __half h2 = __float2half_rn(v.z), h3 = __float2half_rn(v.w);
        __half e0 = __float2half_rn(v.x - __half2float(h0));
        __half e1 = __float2half_rn(v.y - __half2float(h1));
        __half e2 = __float2half_rn(v.z - __half2float(h2));
        __half e3 = __float2half_rn(v.w - __half2float(h3));
        *(__half2*)(sAh + r * SA + c)     = __halves2half2(h0, h1);
        *(__half2*)(sAh + r * SA + c + 2) = __halves2half2(h2, h3);
        *(__half2*)(sAl + r * SA + c)     = __halves2half2(e0, e1);
        *(__half2*)(sAl + r * SA + c + 2) = __halves2half2(e2, e3);
    }

    run_unit(smem, sb, g_leaf_W, g_leaf_bias, 2, curOut, nullptr, row0);
}

// ---------------------------------------------------------------------------
// Tree-level kernel: builds [feat(32) | child0(33) | child1(33) | 0-pad] rows
// ---------------------------------------------------------------------------
__global__ void __launch_bounds__(NT, 3)
int_kernel(const float* __restrict__ int_feat, const float* __restrict__ prev,
           float* __restrict__ curOut, int log2n, float* dfinal)
{
    extern __shared__ char smem[];
    const uint32_t sb = (uint32_t)__cvta_generic_to_shared(smem);
    const int tid = threadIdx.x;
    const int row0 = blockIdx.x * 64;
    const int n = 1 << log2n;

    stage_chunk(sb + OFF_B0, g_int_W, 0); cpa_commit();
    stage_chunk(sb + OFF_B1, g_int_W, 1); cpa_commit();

    __half* sAh = (__half*)(smem + OFF_AH);
    __half* sAl = (__half*)(smem + OFF_AL);
    for (int i = tid; i < 64 * 128; i += NT) {
        int r = i >> 7, c = i & 127;
        int rowg = row0 + r;
        int b  = rowg >> log2n;
        int ii = rowg & (n - 1);
        float v;
        if (c < 32) {
            v = int_feat[((size_t)b * NINT + (n - 1) + ii) * 32 + c];
        } else if (c < 98) {
            v = prev[((size_t)b * (n << 1) + (ii << 1)) * 33 + (c - 32)];
        } else {
            v = 0.f;
        }
        __half h = __float2half_rn(v);
        __half e = __float2half_rn(v - __half2float(h));
        sAh[r * SA + c] = h;
        sAl[r * SA + c] = e;
    }

    run_unit(smem, sb, g_int_W, g_int_bias, 4, curOut, dfinal, row0);
}

// ---------------------------------------------------------------------------
extern "C" void kernel_launch(void* const* d_in, const int* in_sizes, int n_in,
                              void* d_out, int out_size)
{
    const float* leaf_feat = (const float*)d_in[0];
    const float* int_feat  = (const float*)d_in[1];
    const float* lWin  = (const float*)d_in[2];
    const float* lbin  = (const float*)d_in[3];
    const float* lWhid = (const float*)d_in[4];
    const float* lbhid = (const float*)d_in[5];
    const float* lWout = (const float*)d_in[6];
    const float* lbout = (const float*)d_in[7];
    const float* iWin  = (const float*)d_in[8];
    const float* ibin  = (const float*)d_in[9];
    const float* iWhid = (const float*)d_in[10];
    const float* ibhid = (const float*)d_in[11];
    const float* iWout = (const float*)d_in[12];
    const float* ibout = (const float*)d_in[13];
    float* out = (float*)d_out;

    cudaFuncSetAttribute(leaf_kernel, cudaFuncAttributeMaxDynamicSharedMemorySize, SMEM_TOTAL);
    cudaFuncSetAttribute(int_kernel,  cudaFuncAttributeMaxDynamicSharedMemorySize, SMEM_TOTAL);

    float *curA = nullptr, *curB = nullptr;
    cudaGetSymbolAddress((void**)&curA, g_curA);
    cudaGetSymbolAddress((void**)&curB, g_curB);

    prep_kernel<<<256, 256>>>(lWin, lbin, lWhid, lbhid, lWout, lbout,
                              iWin, ibin, iWhid, ibhid, iWout, ibout);

    leaf_kernel<<<(B_ * 1024) / 64, NT, SMEM_TOTAL>>>(leaf_feat, curA);

    float* pin = curA;
    float* pout = curB;
    for (int d = 9; d >= 1; --d) {
        int rows = B_ << d;
        int_kernel<<<rows / 64, NT, SMEM_TOTAL>>>(int_feat, pin, pout, d, nullptr);
        float* t = pin; pin = pout; pout = t;
    }
    int_kernel<<<B_ / 64, NT, SMEM_TOTAL>>>(int_feat, pin, pout, 0, out);
}